// round 8
// baseline (speedup 1.0000x reference)
#include <cuda_runtime.h>
#include <cuda_bf16.h>
#include <cstdint>

typedef __nv_bfloat16 bf16;

#define EMBED 1024
#define TT 512
#define SS 512
#define BATCH 8
#define NHB 128
#define MROWS 4096

// ---------------- scratch (static device globals; no allocation allowed) ----
__device__ bf16 g_q_h[MROWS*EMBED],  g_q_l[MROWS*EMBED];
__device__ bf16 g_k_h[MROWS*EMBED],  g_k_l[MROWS*EMBED];
__device__ bf16 g_v_h[MROWS*EMBED],  g_v_l[MROWS*EMBED];
__device__ bf16 g_Wq_h[EMBED*EMBED], g_Wq_l[EMBED*EMBED];
__device__ bf16 g_Wk_h[EMBED*EMBED], g_Wk_l[EMBED*EMBED];
__device__ bf16 g_Wv_h[EMBED*EMBED], g_Wv_l[EMBED*EMBED];
__device__ bf16 g_Wo_h[EMBED*EMBED], g_Wo_l[EMBED*EMBED];
__device__ bf16 g_qp_h [NHB*TT*64],  g_qp_l [NHB*TT*64];   // [n][t][d]
__device__ bf16 g_kpT_h[NHB*64*SS],  g_kpT_l[NHB*64*SS];   // [n][d][s]
__device__ bf16 g_vp_h [NHB*SS*64],  g_vp_l [NHB*SS*64];   // [n][s][d]
__device__ float g_p [NHB*TT*SS];                          // p_choose (fp32)
__device__ bf16 g_al_h[NHB*TT*SS],   g_al_l[NHB*TT*SS];    // alpha [n][t][s]
__device__ bf16 g_at_h[MROWS*EMBED], g_at_l[MROWS*EMBED];  // merged [t*8+b][h*64+d]

// ============================================================================
// PTX helpers
// ============================================================================
__device__ __forceinline__ uint32_t smem_u32(const void* p) {
    uint32_t a;
    asm("{ .reg .u64 t; cvta.to.shared.u64 t, %1; cvt.u32.u64 %0, t; }"
        : "=r"(a) : "l"(p));
    return a;
}
__device__ __forceinline__ void ldmA(uint32_t r[4], uint32_t addr) {
    asm volatile("ldmatrix.sync.aligned.m8n8.x4.shared.b16 {%0,%1,%2,%3},[%4];"
        : "=r"(r[0]), "=r"(r[1]), "=r"(r[2]), "=r"(r[3]) : "r"(addr));
}
__device__ __forceinline__ void ldmBT(uint32_t r[4], uint32_t addr) {
    asm volatile("ldmatrix.sync.aligned.m8n8.x4.trans.shared.b16 {%0,%1,%2,%3},[%4];"
        : "=r"(r[0]), "=r"(r[1]), "=r"(r[2]), "=r"(r[3]) : "r"(addr));
}
__device__ __forceinline__ void mma16816(float c[4], const uint32_t a[4],
                                         uint32_t b0, uint32_t b1) {
    asm volatile(
        "mma.sync.aligned.m16n8k16.row.col.f32.bf16.bf16.f32 "
        "{%0,%1,%2,%3},{%4,%5,%6,%7},{%8,%9},{%0,%1,%2,%3};"
        : "+f"(c[0]), "+f"(c[1]), "+f"(c[2]), "+f"(c[3])
        : "r"(a[0]), "r"(a[1]), "r"(a[2]), "r"(a[3]), "r"(b0), "r"(b1));
}
__device__ __forceinline__ void cp16(uint32_t dst, const void* src) {
    asm volatile("cp.async.ca.shared.global [%0], [%1], 16;"
        :: "r"(dst), "l"(src));
}
__device__ __forceinline__ void cp_commit() {
    asm volatile("cp.async.commit_group;");
}
template<int N>
__device__ __forceinline__ void cp_wait() {
    asm volatile("cp.async.wait_group %0;" :: "n"(N));
}
__device__ __forceinline__ bf16 tobf(float v) { return __float2bfloat16(v); }

// ============================================================================
// bf16x3 GEMM core: 3-stage cp.async pipeline, ONE barrier per k-tile,
// fragment reuse, precomputed shared addresses.
// acc += Ah*Bh + Ah*Bl + Al*Bh.   Al = Ah + loA elements, Bl = Bh + loB.
// Block = 128 x BN, 256 threads (8 warps, wm=wid&3, wn=wid>>2).
// Dynamic shared memory: caller passes S*(ASZ+BSZ)*2 bytes.
// ============================================================================
#define PIPE_S 3

template<int BN>
__device__ __forceinline__ void gemm_core(
    const bf16* __restrict__ Ah, long loA, int lda,
    const bf16* __restrict__ Bh, long loB, int ldb,
    int K, float acc[2][BN/16][4])
{
    constexpr int NT = BN / 16;
    constexpr int BSTR = BN + 40;            // 20 banks mod 32 -> conflict-free
    constexpr int ASZ = 2 * 128 * 40;        // elements per stage (hi+lo)
    constexpr int BSZ = 2 * 32 * BSTR;
    constexpr uint32_t ALOb = 128 * 40 * 2;  // hi->lo byte offset within stage
    constexpr uint32_t BLOb = 32 * BSTR * 2;
    constexpr uint32_t ASTb = ASZ * 2;       // stage byte strides
    constexpr uint32_t BSTb = BSZ * 2;

    extern __shared__ bf16 smem_pool[];
    bf16* sA = smem_pool;                    // PIPE_S stages of A
    bf16* sB = smem_pool + PIPE_S * ASZ;     // PIPE_S stages of B

    const int tid = threadIdx.x;
    const int lane = tid & 31, wid = tid >> 5;
    const int wm = wid & 3, wn = wid >> 2;
    const int nTiles = K / 32;
    const uint32_t sAu = smem_u32(sA), sBu = smem_u32(sB);

    // ---- cp.async coordinates (precomputed, stage 0) ----
    const int aR = tid >> 2, aC = (tid & 3) * 8;
    const int aR2 = aR + 64;
    const bf16* srcA0 = Ah + aR * lda + aC;
    const bf16* srcA1 = Ah + aR2 * lda + aC;
    const uint32_t dA0 = sAu + (uint32_t)(aR * 40 + aC) * 2;
    const uint32_t dA1 = sAu + (uint32_t)(aR2 * 40 + aC) * 2;
    constexpr int BCH = (BN / 8) * 32 / 256;
    const bf16* srcB[BCH];
    uint32_t dB[BCH];
#pragma unroll
    for (int i = 0; i < BCH; i++) {
        int id = tid + i * 256;
        int rr = id / (BN / 8), cc = (id % (BN / 8)) * 8;
        srcB[i] = Bh + rr * ldb + cc;
        dB[i] = sBu + (uint32_t)(rr * BSTR + cc) * 2;
    }

    // ---- LDSM addresses (precomputed, stage 0) ----
    uint32_t bAddr[NT / 2];
#pragma unroll
    for (int np = 0; np < NT / 2; np++)
        bAddr[np] = sBu + (uint32_t)((lane & 15) * BSTR +
                     wn * (NT * 8) + np * 16 + ((lane >> 4) << 3)) * 2;
    uint32_t aAddr[2];
#pragma unroll
    for (int mt = 0; mt < 2; mt++)
        aAddr[mt] = sAu + (uint32_t)((wm * 32 + mt * 16 + (lane & 15)) * 40 +
                     ((lane >> 4) << 3)) * 2;

    auto loadTile = [&](int st) {
        const uint32_t oA = (uint32_t)st * ASTb, oB = (uint32_t)st * BSTb;
        cp16(dA0 + oA, srcA0);  cp16(dA0 + ALOb + oA, srcA0 + loA);
        cp16(dA1 + oA, srcA1);  cp16(dA1 + ALOb + oA, srcA1 + loA);
        srcA0 += 32; srcA1 += 32;
#pragma unroll
        for (int i = 0; i < BCH; i++) {
            cp16(dB[i] + oB, srcB[i]);
            cp16(dB[i] + BLOb + oB, srcB[i] + loB);
            srcB[i] += 32 * ldb;
        }
    };

    // ---- prologue: stages 0..S-2, one commit group per stage ----
#pragma unroll
    for (int s = 0; s < PIPE_S - 1; s++) {
        if (s < nTiles) loadTile(s);
        cp_commit();
    }

    int stC = 0, stL = PIPE_S - 1;
    for (int i = 0; i < nTiles; i++) {
        cp_wait<PIPE_S - 2>();       // stage i landed (positional group count)
        __syncthreads();             // everyone sees it; everyone done with i-1

        if (i + PIPE_S - 1 < nTiles) loadTile(stL);
        cp_commit();                 // commit (possibly empty) group
        if (++stL == PIPE_S) stL = 0;

        const uint32_t stA = (uint32_t)stC * ASTb;
        const uint32_t stB = (uint32_t)stC * BSTb;
        if (++stC == PIPE_S) stC = 0;

#pragma unroll
        for (int kk = 0; kk < 2; kk++) {
            const uint32_t kA = stA + (kk ? 32u : 0u);              // +16 elems
            const uint32_t kB = stB + (kk ? 16u * BSTR * 2u : 0u);  // +16 rows
            uint32_t bh[NT][2];
#pragma unroll
            for (int np = 0; np < NT / 2; np++) {
                uint32_t rr[4];
                ldmBT(rr, bAddr[np] + kB);
                bh[2 * np][0] = rr[0]; bh[2 * np][1] = rr[1];
                bh[2 * np + 1][0] = rr[2]; bh[2 * np + 1][1] = rr[3];
            }
            uint32_t ah[2][4], al[2][4];
#pragma unroll
            for (int mt = 0; mt < 2; mt++) {
                ldmA(ah[mt], aAddr[mt] + kA);
                ldmA(al[mt], aAddr[mt] + ALOb + kA);
            }
#pragma unroll
            for (int mt = 0; mt < 2; mt++)
#pragma unroll
                for (int nt = 0; nt < NT; nt++) {
                    mma16816(acc[mt][nt], ah[mt], bh[nt][0], bh[nt][1]);
                    mma16816(acc[mt][nt], al[mt], bh[nt][0], bh[nt][1]);
                }
#pragma unroll
            for (int np = 0; np < NT / 2; np++) {
                uint32_t rr[4];
                ldmBT(rr, bAddr[np] + BLOb + kB);
#pragma unroll
                for (int mt = 0; mt < 2; mt++) {
                    mma16816(acc[mt][2 * np],     ah[mt], rr[0], rr[1]);
                    mma16816(acc[mt][2 * np + 1], ah[mt], rr[2], rr[3]);
                }
            }
        }
    }
}

#define SMEM_BN128 (PIPE_S * (2*128*40 + 2*32*168) * 2)   /* 125952 B */
#define SMEM_BN64  (PIPE_S * (2*128*40 + 2*32*104) * 2)   /* 101376 B */

#define EPI_ROW(mt, r)     (wm * 32 + (mt) * 16 + (lane >> 2) + (((r) >> 1) << 3))
#define EPI_COL(nt, r, NT) (wn * ((NT) * 8) + (nt) * 8 + ((lane & 3) << 1) + ((r) & 1))

// ============================================================================
// split kernels: fp32 -> (bf16 hi, bf16 lo). blockIdx.y selects tensor.
// ============================================================================
__global__ void split_act_kernel(const float* __restrict__ q,
                                 const float* __restrict__ k,
                                 const float* __restrict__ v)
{
    const float* x; bf16 *h, *l;
    switch (blockIdx.y) {
        case 0:  x = q; h = g_q_h; l = g_q_l; break;
        case 1:  x = k; h = g_k_h; l = g_k_l; break;
        default: x = v; h = g_v_h; l = g_v_l; break;
    }
    int i = blockIdx.x * blockDim.x + threadIdx.x;
    float val = x[i];
    bf16 hv = tobf(val);
    h[i] = hv;
    l[i] = tobf(val - __bfloat162float(hv));
}

__global__ void split_w_kernel(const float* __restrict__ Wq,
                               const float* __restrict__ Wk,
                               const float* __restrict__ Wv,
                               const float* __restrict__ Wo)
{
    const float* x; bf16 *h, *l;
    switch (blockIdx.y) {
        case 0:  x = Wq; h = g_Wq_h; l = g_Wq_l; break;
        case 1:  x = Wk; h = g_Wk_h; l = g_Wk_l; break;
        case 2:  x = Wv; h = g_Wv_h; l = g_Wv_l; break;
        default: x = Wo; h = g_Wo_h; l = g_Wo_l; break;
    }
    int i = blockIdx.x * blockDim.x + threadIdx.x;
    float val = x[i];
    bf16 hv = tobf(val);
    h[i] = hv;
    l[i] = tobf(val - __bfloat162float(hv));
}

// ============================================================================
// Merged projection GEMM: blockIdx.z = which (0=Q,1=K,2=V).
// ============================================================================
__global__ __launch_bounds__(256) void proj_mma_kernel()
{
    const int which = blockIdx.z;
    const bf16 *Ah, *Wh;
    long loA, loW;
    if (which == 0)      { Ah = g_q_h; loA = g_q_l - g_q_h; Wh = g_Wq_h; loW = g_Wq_l - g_Wq_h; }
    else if (which == 1) { Ah = g_k_h; loA = g_k_l - g_k_h; Wh = g_Wk_h; loW = g_Wk_l - g_Wk_h; }
    else                 { Ah = g_v_h; loA = g_v_l - g_v_h; Wh = g_Wv_h; loW = g_Wv_l - g_Wv_h; }
    const float scale = (which == 0) ? 0.125f : 1.0f;

    const int bm = blockIdx.y * 128, bn = blockIdx.x * 128;
    float acc[2][8][4];
#pragma unroll
    for (int i = 0; i < 2; i++)
#pragma unroll
        for (int j = 0; j < 8; j++)
#pragma unroll
            for (int r = 0; r < 4; r++) acc[i][j][r] = 0.f;

    gemm_core<128>(Ah + bm * 1024, loA, 1024, Wh + bn, loW, 1024, 1024, acc);

    const int lane = threadIdx.x & 31, wid = threadIdx.x >> 5;
    const int wm = wid & 3, wn = wid >> 2;
    bf16 *dh, *dl;
    if (which == 0)      { dh = g_qp_h;  dl = g_qp_l;  }
    else if (which == 1) { dh = g_kpT_h; dl = g_kpT_l; }
    else                 { dh = g_vp_h;  dl = g_vp_l;  }

    if (which == 1) {
#pragma unroll
        for (int mt = 0; mt < 2; mt++)
#pragma unroll
            for (int nt = 0; nt < 8; nt++)
#pragma unroll
                for (int r = 0; r < 4; r++) {
                    int row = bm + EPI_ROW(mt, r);
                    int col = bn + EPI_COL(nt, r, 8);
                    int t = row >> 3, b = row & 7;
                    int h = col >> 6, d = col & 63;
                    int n = b * 16 + h;
                    float v = acc[mt][nt][r];
                    int idx = (n * 64 + d) * 512 + t;
                    bf16 hv = tobf(v);
                    dh[idx] = hv;
                    dl[idx] = tobf(v - __bfloat162float(hv));
                }
    } else {
#pragma unroll
        for (int mt = 0; mt < 2; mt++)
#pragma unroll
            for (int nt = 0; nt < 8; nt++)
#pragma unroll
                for (int r2 = 0; r2 < 4; r2 += 2) {
                    int row = bm + EPI_ROW(mt, r2);
                    int col = bn + EPI_COL(nt, r2, 8);   // even
                    int t = row >> 3, b = row & 7;
                    int h = col >> 6, d = col & 63;
                    int n = b * 16 + h;
                    int idx = (n * 512 + t) * 64 + d;
                    float v0 = acc[mt][nt][r2] * scale;
                    float v1 = acc[mt][nt][r2 + 1] * scale;
                    bf16 h0 = tobf(v0), h1 = tobf(v1);
                    __nv_bfloat162 hp; hp.x = h0; hp.y = h1;
                    __nv_bfloat162 lp;
                    lp.x = tobf(v0 - __bfloat162float(h0));
                    lp.y = tobf(v1 - __bfloat162float(h1));
                    *(__nv_bfloat162*)&dh[idx] = hp;
                    *(__nv_bfloat162*)&dl[idx] = lp;
                }
    }
}

// ============================================================================
// Energy + sigmoid -> g_p (fp32)
// ============================================================================
__global__ __launch_bounds__(256) void energy_mma_kernel(const float* __restrict__ ebias)
{
    const int n = blockIdx.z;
    const int t0 = blockIdx.y * 128, s0 = blockIdx.x * 128;
    float acc[2][8][4];
#pragma unroll
    for (int i = 0; i < 2; i++)
#pragma unroll
        for (int j = 0; j < 8; j++)
#pragma unroll
            for (int r = 0; r < 4; r++) acc[i][j][r] = 0.f;

    gemm_core<128>(g_qp_h + n * 512 * 64 + t0 * 64, g_qp_l - g_qp_h, 64,
                   g_kpT_h + n * 64 * 512 + s0,     g_kpT_l - g_kpT_h, 512,
                   64, acc);

    const int lane = threadIdx.x & 31, wid = threadIdx.x >> 5;
    const int wm = wid & 3, wn = wid >> 2;
    const float eb = ebias[0];
#pragma unroll
    for (int mt = 0; mt < 2; mt++)
#pragma unroll
        for (int nt = 0; nt < 8; nt++)
#pragma unroll
            for (int r2 = 0; r2 < 4; r2 += 2) {
                int t = t0 + EPI_ROW(mt, r2);
                int s = s0 + EPI_COL(nt, r2, 8);
                float e0 = acc[mt][nt][r2] + eb;
                float e1 = acc[mt][nt][r2 + 1] + eb;
                float2 pv;
                pv.x = 1.f / (1.f + __expf(-e0));
                pv.y = 1.f / (1.f + __expf(-e1));
                *(float2*)&g_p[(n * 512 + t) * 512 + s] = pv;
            }
}

// ============================================================================
// Fused recurrence — 2 barriers per t-step.  The mass-preservation write of
// row t's last column is deferred to step t+1 (sh_m double-buffered).
// One block per n (128), 512 threads (one per s).
// ============================================================================
__global__ __launch_bounds__(512) void recurrence_kernel()
{
    const int s = threadIdx.x;
    const int n = blockIdx.x;
    const int lane = s & 31, wid = s >> 5;
    const int base = n * 512 * 512 + s;

    __shared__ float sh_sw[16], sh_sp[16];
    __shared__ float sh_pw[16], sh_pp[16];
    __shared__ float sh_m[2][16];

    // ---- prologue: exclusive cumprod for t=0 ----
    float p = g_p[base];
    float cl, pc;
    {
        float v = 1.f - p;
#pragma unroll
        for (int o = 1; o < 32; o <<= 1) {
            float u = __shfl_up_sync(0xffffffffu, v, o);
            if (lane >= o) v *= u;
        }
        if (lane == 31) sh_pw[wid] = v;
        __syncthreads();
        if (wid == 0) {
            float w = (lane < 16) ? sh_pw[lane] : 1.f;
#pragma unroll
            for (int o = 1; o < 16; o <<= 1) {
                float u = __shfl_up_sync(0xffffffffu, w, o);
                if (lane >= o) w *= u;
            }
            if (lane < 16) sh_pp[lane] = w;
        }
        __syncthreads();
        float woff = (wid > 0) ? sh_pp[wid - 1] : 1.f;
        float inclp = v * woff;
        float cp = __shfl_up_sync(0xffffffffu, inclp, 1);
        if (lane == 0) cp = woff;
        if (s == 0) cp = 1.f;
        cl = fminf(fmaxf(cp, 1e-6f), 1.f);
        pc = p * cp;
    }
    float aprev = (s == 0) ? 1.f : 0.f;

    for (int t = 0; t < 512; t++) {
        float pnext = (t < 511) ? g_p[base + (t + 1) * 512] : 0.f;

        // interleaved scans: sum of aprev/cl (row t), product of 1-pnext (t+1)
        float u2 = aprev / cl;
        float vb = 1.f - pnext;
#pragma unroll
        for (int o = 1; o < 32; o <<= 1) {
            float uu = __shfl_up_sync(0xffffffffu, u2, o);
            float vv = __shfl_up_sync(0xffffffffu, vb, o);
            if (lane >= o) { u2 += uu; vb *= vv; }
        }
        if (lane == 31) { sh_sw[wid] = u2; sh_pw[wid] = vb; }
        __syncthreads();                                   // barrier 1
        if (wid == 0) {
            float w = (lane < 16) ? sh_sw[lane] : 0.f;
#pragma unroll
            for (int o = 1; o < 16; o <<= 1) {
                float uu = __shfl_up_sync(0xffffffffu, w, o);
                if (lane >= o) w += uu;
            }
            if (lane < 16) sh_sp[lane] = w;
        } else if (wid == 1) {
            float w = (lane < 16) ? sh_pw[lane] : 1.f;
#pragma unroll
            for (int o = 1; o < 16; o <<= 1) {
                float uu = __shfl_up_sync(0xffffffffu, w, o);
                if (lane >= o) w *= uu;
            }
            if (lane < 16) sh_pp[lane] = w;
        }
        __syncthreads();                                   // barrier 2

        float incl2 = u2 + ((wid > 0) ? sh_sp[wid - 1] : 0.f);
        float araw = fminf(fmaxf(pc * incl2, 0.f), 1.f);

        // next-row cumprod finish
        float woff = (wid > 0) ? sh_pp[wid - 1] : 1.f;
        float inclp = vb * woff;
        float cpn = __shfl_up_sync(0xffffffffu, inclp, 1);
        if (lane == 0) cpn = woff;
        if (s == 0) cpn = 1.f;
        float cln = fminf(fmaxf(cpn, 1e-6f), 1.f);
        float pcn = pnext * cpn;

        // store non-last columns of row t
        if (s < 511) {
            bf16 hv = tobf(araw);
            g_al_h[base + t * 512] = hv;
            g_al_l[base + t * 512] = tobf(araw - __bfloat162float(hv));
        }

        // warp totals of clipped araw (s<511) for mass preservation
        float yv = (s < 511) ? araw : 0.f;
#pragma unroll
        for (int o = 16; o > 0; o >>= 1)
            yv += __shfl_xor_sync(0xffffffffu, yv, o);
        if (lane == 0) sh_m[t & 1][wid] = yv;

        // deferred: finish row t-1's last column (its sh_m is barrier-published)
        if (t > 0 && s == 511) {
            float total = 0.f;
#pragma unroll
            for (int i = 0; i < 16; i++) total += sh_m[(t - 1) & 1][i];
            float aout = 1.f - fminf(fmaxf(total, 0.f), 1.f);
            bf16 hv = tobf(aout);
            g_al_h[base + (t - 1) * 512] = hv;
            g_al_l[base + (t - 1) * 512] = tobf(aout - __bfloat162float(hv));
        }

        aprev = araw;
        cl = cln;
        pc = pcn;
    }

    // epilogue: row 511's last column
    __syncthreads();
    if (s == 511) {
        float total = 0.f;
#pragma unroll
        for (int i = 0; i < 16; i++) total += sh_m[511 & 1][i];
        float aout = 1.f - fminf(fmaxf(total, 0.f), 1.f);
        bf16 hv = tobf(aout);
        g_al_h[base + 511 * 512] = hv;
        g_al_l[base + 511 * 512] = tobf(aout - __bfloat162float(hv));
    }
}

// ============================================================================
// attn = alpha @ vp  (per n: [512x512]@[512x64]) -> merged hi/lo.
// ============================================================================
__global__ __launch_bounds__(256) void attnv_mma_kernel()
{
    const int n = blockIdx.z;
    const int t0 = blockIdx.y * 128;
    float acc[2][4][4];
#pragma unroll
    for (int i = 0; i < 2; i++)
#pragma unroll
        for (int j = 0; j < 4; j++)
#pragma unroll
            for (int r = 0; r < 4; r++) acc[i][j][r] = 0.f;

    gemm_core<64>(g_al_h + n * 512 * 512 + t0 * 512, g_al_l - g_al_h, 512,
                  g_vp_h + n * 512 * 64,             g_vp_l - g_vp_h, 64,
                  512, acc);

    const int lane = threadIdx.x & 31, wid = threadIdx.x >> 5;
    const int wm = wid & 3, wn = wid >> 2;
    const int b = n >> 4, h = n & 15;
#pragma unroll
    for (int mt = 0; mt < 2; mt++)
#pragma unroll
        for (int nt = 0; nt < 4; nt++)
#pragma unroll
            for (int r2 = 0; r2 < 4; r2 += 2) {
                int t = t0 + EPI_ROW(mt, r2);
                int d = EPI_COL(nt, r2, 4);
                int idx = (t * 8 + b) * 1024 + h * 64 + d;
                float v0 = acc[mt][nt][r2], v1 = acc[mt][nt][r2 + 1];
                bf16 h0 = tobf(v0), h1 = tobf(v1);
                __nv_bfloat162 hp; hp.x = h0; hp.y = h1;
                __nv_bfloat162 lp;
                lp.x = tobf(v0 - __bfloat162float(h0));
                lp.y = tobf(v1 - __bfloat162float(h1));
                *(__nv_bfloat162*)&g_at_h[idx] = hp;
                *(__nv_bfloat162*)&g_at_l[idx] = lp;
            }
}

// ============================================================================
// Output projection: out = attn[4096x1024] @ Wo + bo (fp32 out)
// ============================================================================
__global__ __launch_bounds__(256) void out_mma_kernel(
    const float* __restrict__ bias, float* __restrict__ out)
{
    const int bm = blockIdx.y * 128, bn = blockIdx.x * 128;
    float acc[2][8][4];
#pragma unroll
    for (int i = 0; i < 2; i++)
#pragma unroll
        for (int j = 0; j < 8; j++)
#pragma unroll
            for (int r = 0; r < 4; r++) acc[i][j][r] = 0.f;

    gemm_core<128>(g_at_h + bm * 1024, g_at_l - g_at_h, 1024,
                   g_Wo_h + bn,        g_Wo_l - g_Wo_h, 1024, 1024, acc);

    const int lane = threadIdx.x & 31, wid = threadIdx.x >> 5;
    const int wm = wid & 3, wn = wid >> 2;
#pragma unroll
    for (int mt = 0; mt < 2; mt++)
#pragma unroll
        for (int nt = 0; nt < 8; nt++)
#pragma unroll
            for (int r2 = 0; r2 < 4; r2 += 2) {
                int row = bm + EPI_ROW(mt, r2);
                int col = bn + EPI_COL(nt, r2, 8);
                float2 ov;
                ov.x = acc[mt][nt][r2]     + bias[col];
                ov.y = acc[mt][nt][r2 + 1] + bias[col + 1];
                *(float2*)&out[row * 1024 + col] = ov;
            }
}

// ============================================================================
extern "C" void kernel_launch(void* const* d_in, const int* in_sizes, int n_in,
                              void* d_out, int out_size)
{
    const float* q  = (const float*)d_in[0];
    const float* k  = (const float*)d_in[1];
    const float* v  = (const float*)d_in[2];
    const float* Wq = (const float*)d_in[3];
    const float* Wk = (const float*)d_in[4];
    const float* Wv = (const float*)d_in[5];
    const float* Wo = (const float*)d_in[6];
    const float* bo = (const float*)d_in[7];
    const float* eb = (const float*)d_in[8];
    float* out = (float*)d_out;

    static bool attr_done = false;
    if (!attr_done) {
        cudaFuncSetAttribute(proj_mma_kernel,
            cudaFuncAttributeMaxDynamicSharedMemorySize, SMEM_BN128);
        cudaFuncSetAttribute(energy_mma_kernel,
            cudaFuncAttributeMaxDynamicSharedMemorySize, SMEM_BN128);
        cudaFuncSetAttribute(out_mma_kernel,
            cudaFuncAttributeMaxDynamicSharedMemorySize, SMEM_BN128);
        cudaFuncSetAttribute(attnv_mma_kernel,
            cudaFuncAttributeMaxDynamicSharedMemorySize, SMEM_BN64);
        attr_done = true;
    }

    split_act_kernel<<<dim3(MROWS * EMBED / 256, 3), 256>>>(q, k, v);
    split_w_kernel<<<dim3(EMBED * EMBED / 256, 4), 256>>>(Wq, Wk, Wv, Wo);

    proj_mma_kernel<<<dim3(8, 32, 3), 256, SMEM_BN128>>>();
    energy_mma_kernel<<<dim3(4, 4, 128), 256, SMEM_BN128>>>(eb);
    recurrence_kernel<<<128, 512>>>();
    attnv_mma_kernel<<<dim3(1, 4, 128), 256, SMEM_BN64>>>();
    out_mma_kernel<<<dim3(8, 32), 256, SMEM_BN128>>>(bo, out);
}